// round 11
// baseline (speedup 1.0000x reference)
#include <cuda_runtime.h>
#include <cuda_fp16.h>
#include <math.h>
#include <stdint.h>

// ---------------------------------------------------------------- constants
#define NROWS 32768          // B*L
#define EQ    1280
#define KDIM  1280
#define VQ    32
#define PQ    496
#define N2P   640            // padded width of second GEMM (528 -> 640)
#define LN_EPS 1e-12f
#define KC    64             // K per chunk (4 ks-steps of 16)
#define NCH   (KDIM / KC)    // 20
#define NSTG  3              // cp.async pipeline stages

// ---------------------------------------------------------------- scratch
__device__ __half g_hf[(size_t)NROWS * EQ];          // post-GELU hidden (fp16)
__device__ float g_l2[(size_t)NROWS * N2P];          // [pi_logits | Theta | pad]
__device__ __half g_xf[(size_t)NROWS * KDIM];        // hx fp16
__device__ __half g_af[(size_t)NROWS * KDIM];        // LN(h) fp16
__device__ __half g_w1f[(size_t)EQ * KDIM];          // dense_w^T fp16 [n][k]
__device__ __half g_w2f[(size_t)N2P * KDIM];         // packed [theta|Theta]^T fp16
__device__ float g_b2[N2P];

// ---------------------------------------------------------------- PTX utils
__device__ __forceinline__ uint32_t smem_u32(const void* p) {
    uint32_t a;
    asm("{ .reg .u64 t; cvta.to.shared.u64 t, %1; cvt.u32.u64 %0, t; }"
        : "=r"(a) : "l"(p));
    return a;
}
__device__ __forceinline__ void ldsm4(uint32_t* r, uint32_t addr) {
    asm volatile("ldmatrix.sync.aligned.m8n8.x4.shared.b16 {%0,%1,%2,%3}, [%4];"
                 : "=r"(r[0]), "=r"(r[1]), "=r"(r[2]), "=r"(r[3]) : "r"(addr));
}
__device__ __forceinline__ void mma16816(float* d, const uint32_t* a,
                                         const uint32_t* b) {
    asm volatile(
        "mma.sync.aligned.m16n8k16.row.col.f32.f16.f16.f32 "
        "{%0,%1,%2,%3}, {%4,%5,%6,%7}, {%8,%9}, {%0,%1,%2,%3};"
        : "+f"(d[0]), "+f"(d[1]), "+f"(d[2]), "+f"(d[3])
        : "r"(a[0]), "r"(a[1]), "r"(a[2]), "r"(a[3]), "r"(b[0]), "r"(b[1]));
}
__device__ __forceinline__ void cpasync16(uint32_t dst, const void* src) {
    asm volatile("cp.async.cg.shared.global [%0], [%1], 16;"
                 :: "r"(dst), "l"(src));
}
#define CP_COMMIT() asm volatile("cp.async.commit_group;" ::: "memory")
#define CP_WAIT1()  asm volatile("cp.async.wait_group 1;" ::: "memory")
#define CP_WAIT0()  asm volatile("cp.async.wait_group 0;" ::: "memory")

// ---------------------------------------------------------------- prep kernels
__global__ void conv_x_kernel(const float* __restrict__ x) {
    size_t idx = (size_t)blockIdx.x * blockDim.x + threadIdx.x;
    if (idx >= (size_t)NROWS * KDIM / 4) return;
    float4 v = ((const float4*)x)[idx];
    ushort4 hv = make_ushort4(__half_as_ushort(__float2half_rn(v.x)),
                              __half_as_ushort(__float2half_rn(v.y)),
                              __half_as_ushort(__float2half_rn(v.z)),
                              __half_as_ushort(__float2half_rn(v.w)));
    ((ushort4*)g_xf)[idx] = hv;
}

__global__ void conv_w1_kernel(const float* __restrict__ w) {
    int idx = blockIdx.x * blockDim.x + threadIdx.x;
    if (idx >= EQ * KDIM) return;
    int n = idx / KDIM;
    int k = idx - n * KDIM;
    g_w1f[idx] = __float2half_rn(w[(size_t)k * EQ + n]);
}

__global__ void conv_w2_kernel(const float* __restrict__ tw,
                               const float* __restrict__ tb,
                               const float* __restrict__ Tw,
                               const float* __restrict__ Tb) {
    int idx = blockIdx.x * blockDim.x + threadIdx.x;
    if (idx < N2P * KDIM) {
        int n = idx / KDIM;
        int k = idx - n * KDIM;
        float v = 0.0f;
        if (n < VQ)           v = tw[(size_t)k * VQ + n];
        else if (n < VQ + PQ) v = Tw[(size_t)k * PQ + (n - VQ)];
        g_w2f[idx] = __float2half_rn(v);
    }
    if (idx < N2P)
        g_b2[idx] = (idx < VQ) ? tb[idx] : (idx < VQ + PQ ? Tb[idx - VQ] : 0.0f);
}

// ---------------------------------------------------------------- GEMM (HMMA)
// C[128x128] = A @ B^T, fp16 operands, fp32 accumulate, K-major.
// KC=64 (4 ks-steps), 3-stage cp.async pipeline, ONE barrier per 64 MMAs,
// register double-buffered fragments, per-CTA chunk-order rotation to
// desynchronize the two co-resident CTAs' memory/MMA phases. 2 CTAs/SM.
// SMEM per stage: 2 pieces (A, B), each 128 rows x 128B, stride 144B.
template <bool GELU, typename OutT>
__global__ void __launch_bounds__(256, 2)
gemm_mma_kernel(const __half* __restrict__ Af,
                const __half* __restrict__ Bf,
                const float* __restrict__ bias, OutT* __restrict__ C,
                int ldc) {
    extern __shared__ char sm[];
    const uint32_t sb = smem_u32(sm);
    constexpr uint32_t RS = 144;
    constexpr uint32_t PIECE = 128 * RS;   // 18432
    constexpr uint32_t STAGE = 2 * PIECE;  // 36864

    int tid = threadIdx.x;
    int lane = tid & 31;
    int wid = tid >> 5;
    int wm = (wid & 3) * 32;
    int wn = (wid >> 2) * 64;
    int m0 = blockIdx.y * 128;
    int n0 = blockIdx.x * 128;

    // phase rotation: odd CTAs start halfway through the k-chunks
    int start = ((blockIdx.x ^ blockIdx.y) & 1) * (NCH / 2);

    // cp.async mapping: thread -> (row = tid>>1, 64B half of the 128B row)
    int lr = tid >> 1;
    int hf = (tid & 1);
    const __half* pA = Af + (size_t)(m0 + lr) * KDIM + hf * 32;
    const __half* pB = Bf + (size_t)(n0 + lr) * KDIM + hf * 32;
    uint32_t sOff = (uint32_t)lr * RS + (uint32_t)hf * 64;

    auto issue = [&](int c) {
        int kc = c + start;
        if (kc >= NCH) kc -= NCH;
        uint32_t d = sb + (uint32_t)(c % NSTG) * STAGE + sOff;
        size_t g = (size_t)kc * KC;
        cpasync16(d,              pA + g);
        cpasync16(d + 16,         pA + g + 8);
        cpasync16(d + 32,         pA + g + 16);
        cpasync16(d + 48,         pA + g + 24);
        cpasync16(d + PIECE,      pB + g);
        cpasync16(d + PIECE + 16, pB + g + 8);
        cpasync16(d + PIECE + 32, pB + g + 16);
        cpasync16(d + PIECE + 48, pB + g + 24);
        CP_COMMIT();
    };

    // ldmatrix per-lane offsets
    int rA = (lane & 7) + ((lane >> 3) & 1) * 8;
    uint32_t kA = (uint32_t)((lane >> 4) & 1) * 16;
    int rB = (lane & 7) + ((lane >> 4) & 1) * 8;
    uint32_t kB = (uint32_t)((lane >> 3) & 1) * 16;

    auto ldfrag = [&](uint32_t st, uint32_t kbyte, uint32_t (*ah)[4],
                      uint32_t (*bh)[2]) {
#pragma unroll
        for (int mf = 0; mf < 2; mf++)
            ldsm4(ah[mf], st + (uint32_t)(wm + mf * 16 + rA) * RS + kbyte + kA);
#pragma unroll
        for (int g = 0; g < 4; g++) {
            uint32_t t[4];
            ldsm4(t,
                  st + PIECE + (uint32_t)(wn + g * 16 + rB) * RS + kbyte + kB);
            bh[2 * g][0] = t[0]; bh[2 * g][1] = t[1];
            bh[2 * g + 1][0] = t[2]; bh[2 * g + 1][1] = t[3];
        }
    };

    float acc[2][8][4];
#pragma unroll
    for (int i = 0; i < 2; i++)
#pragma unroll
        for (int j = 0; j < 8; j++)
#pragma unroll
            for (int q = 0; q < 4; q++) acc[i][j][q] = 0.0f;

    uint32_t a0[2][4], b0[8][2];   // fragment ping
    uint32_t a1[2][4], b1[8][2];   // fragment pong

#define MMA_ALL(A, B)                                                         \
    _Pragma("unroll") for (int mf = 0; mf < 2; mf++)                          \
        _Pragma("unroll") for (int nf = 0; nf < 8; nf++)                      \
            mma16816(acc[mf][nf], (A)[mf], (B)[nf]);

    issue(0);
    issue(1);
    CP_WAIT1();          // chunk 0 landed
    __syncthreads();
    ldfrag(sb, 0, a0, b0);

    for (int c = 0; c < NCH; c++) {
        uint32_t st = sb + (uint32_t)(c % NSTG) * STAGE;
        ldfrag(st, 32, a1, b1);
        MMA_ALL(a0, b0);                    // ks0
        ldfrag(st, 64, a0, b0);
        MMA_ALL(a1, b1);                    // ks1
        ldfrag(st, 96, a1, b1);
        MMA_ALL(a0, b0);                    // ks2

        if (c + 1 < NCH) {
            CP_WAIT0();                     // chunk c+1 landed
            __syncthreads();                // retire readers of buf (c+2)%3
            if (c + 2 < NCH) issue(c + 2);
            ldfrag(sb + (uint32_t)((c + 1) % NSTG) * STAGE, 0, a0, b0);
        }
        MMA_ALL(a1, b1);                    // ks3
    }
#undef MMA_ALL

    // epilogue: bias (+ GELU); OutT = __half (GEMM1) or float (GEMM2)
    int tr = lane >> 2;
    int tc = (lane & 3) * 2;
#pragma unroll
    for (int mf = 0; mf < 2; mf++) {
#pragma unroll
        for (int nf = 0; nf < 8; nf++) {
            int col = n0 + wn + nf * 8 + tc;
            float2 bb = *(const float2*)&bias[col];
            int r1 = m0 + wm + mf * 16 + tr;
#pragma unroll
            for (int h = 0; h < 2; h++) {
                float v0 = acc[mf][nf][2 * h + 0] + bb.x;
                float v1 = acc[mf][nf][2 * h + 1] + bb.y;
                if (GELU) {
                    v0 = 0.5f * v0 * (1.0f + erff(v0 * 0.70710678118654752f));
                    v1 = 0.5f * v1 * (1.0f + erff(v1 * 0.70710678118654752f));
                }
                if constexpr (sizeof(OutT) == 2) {
                    __half2 hv = __floats2half2_rn(v0, v1);
                    *(__half2*)&C[(size_t)(r1 + 8 * h) * ldc + col] = hv;
                } else {
                    *(float2*)&C[(size_t)(r1 + 8 * h) * ldc + col] =
                        make_float2(v0, v1);
                }
            }
        }
    }
}

// ---------------------------------------------------------------- LayerNorm
__device__ __forceinline__ float block_reduce_sum(float v) {
    __shared__ float sh[8];
#pragma unroll
    for (int o = 16; o > 0; o >>= 1) v += __shfl_xor_sync(0xffffffffu, v, o);
    int lane = threadIdx.x & 31, wid = threadIdx.x >> 5;
    if (lane == 0) sh[wid] = v;
    __syncthreads();
    v = (lane < 8) ? sh[lane] : 0.0f;
#pragma unroll
    for (int o = 4; o > 0; o >>= 1) v += __shfl_xor_sync(0xffffffffu, v, o);
    v = __shfl_sync(0xffffffffu, v, 0);
    __syncthreads();
    return v;
}

// LN reads fp16 h, computes stats in fp32, writes fp16.
__global__ void ln_kernel(const __half* __restrict__ h,
                          const float* __restrict__ g,
                          const float* __restrict__ b) {
    size_t r = blockIdx.x;
    const __half* row = h + r * EQ;
    int t = threadIdx.x;
    float x[5];
    float s = 0.0f;
#pragma unroll
    for (int i = 0; i < 5; i++) {
        x[i] = __half2float(row[t + i * 256]);
        s += x[i];
    }
    float mu = block_reduce_sum(s) * (1.0f / EQ);
    float v = 0.0f;
#pragma unroll
    for (int i = 0; i < 5; i++) { float d = x[i] - mu; v += d * d; }
    float var = block_reduce_sum(v) * (1.0f / EQ);
    float inv = rsqrtf(var + LN_EPS);
#pragma unroll
    for (int i = 0; i < 5; i++) {
        int c = t + i * 256;
        float y = (x[i] - mu) * inv * g[c] + b[c];
        g_af[r * EQ + c] = __float2half_rn(y);
    }
}

// ---------------------------------------------------------------- finalize
__global__ void __launch_bounds__(256)
finalize_kernel(const int* __restrict__ mask32,
                float* __restrict__ qOut, float* __restrict__ piOut) {
    __shared__ float th[8][512];
    __shared__ float psq[8][32];
    __shared__ float mf[32];

    int lane = threadIdx.x;
    int w = threadIdx.y;
    size_t r = (size_t)blockIdx.x * 8 + w;

    if (w == 0) mf[lane] = (mask32[lane] != 0) ? 1.0f : 0.0f;
    __syncthreads();

    const float* base = g_l2 + r * N2P;

    bool mk = mf[lane] > 0.5f;
    float x = base[lane];
    float xm = mk ? x : -INFINITY;
    float mx = xm;
#pragma unroll
    for (int o = 16; o > 0; o >>= 1)
        mx = fmaxf(mx, __shfl_xor_sync(0xffffffffu, mx, o));
    float e = mk ? expf(xm - mx) : 0.0f;
    float ssum = e;
#pragma unroll
    for (int o = 16; o > 0; o >>= 1)
        ssum += __shfl_xor_sync(0xffffffffu, ssum, o);

    if (piOut) piOut[r * VQ + lane] = e / ssum;
    float logpi = xm - mx - logf(ssum);
    psq[w][lane] = mk ? expf(0.5f * logpi) : 1.0f;

    for (int idx = lane; idx < PQ; idx += 32) {
        float t = base[VQ + idx];
        th[w][idx] = fmaxf(t, 0.0f) + log1pf(expf(-fabsf(t)));
    }
    __syncwarp();

    int i = lane;
    float mi = mf[i];
    float inv = 1.0f / psq[w][i];
    float q[32];
    float rs = 0.0f;
#pragma unroll
    for (int j = 0; j < 32; j++) {
        float val = 0.0f;
        if (j != i) {
            int lo = min(i, j), hi = max(i, j);
            int idx = lo * VQ - (lo * (lo + 1)) / 2 + (hi - lo - 1);
            val = th[w][idx] * mi * mf[j] * psq[w][j] * inv;
        }
        q[j] = val;
        rs += val;
    }
#pragma unroll
    for (int j = 0; j < 32; j++)
        if (j == i) q[j] = -rs;

    float* out = qOut + r * (VQ * VQ) + (size_t)i * VQ;
#pragma unroll
    for (int j = 0; j < 32; j += 4)
        *(float4*)(out + j) = make_float4(q[j], q[j + 1], q[j + 2], q[j + 3]);
}

// ---------------------------------------------------------------- launch
extern "C" void kernel_launch(void* const* d_in, const int* in_sizes, int n_in,
                              void* d_out, int out_size) {
    const float* hx      = (const float*)d_in[0];
    const int*   vmask   = (const int*)d_in[1];
    const float* dense_w = (const float*)d_in[2];
    const float* dense_b = (const float*)d_in[3];
    const float* ln_g    = (const float*)d_in[4];
    const float* ln_b    = (const float*)d_in[5];
    const float* theta_w = (const float*)d_in[6];
    const float* theta_b = (const float*)d_in[7];
    const float* Theta_w = (const float*)d_in[8];
    const float* Theta_b = (const float*)d_in[9];

    float *l2ptr, *b2ptr;
    __half *hfp, *xf, *af, *w1f, *w2f;
    cudaGetSymbolAddress((void**)&hfp, g_hf);
    cudaGetSymbolAddress((void**)&l2ptr, g_l2);
    cudaGetSymbolAddress((void**)&b2ptr, g_b2);
    cudaGetSymbolAddress((void**)&xf, g_xf);
    cudaGetSymbolAddress((void**)&af, g_af);
    cudaGetSymbolAddress((void**)&w1f, g_w1f);
    cudaGetSymbolAddress((void**)&w2f, g_w2f);

    const size_t Q_ELEMS = (size_t)NROWS * VQ * VQ;
    const size_t PI_ELEMS = (size_t)NROWS * VQ;
    float* qOut = (float*)d_out;
    float* piOut = ((size_t)out_size >= Q_ELEMS + PI_ELEMS) ? (qOut + Q_ELEMS)
                                                            : nullptr;

    const int SMEM = NSTG * 2 * 128 * 144;   // 110592 bytes -> 2 CTAs/SM
    cudaFuncSetAttribute(gemm_mma_kernel<true, __half>,
                         cudaFuncAttributeMaxDynamicSharedMemorySize, SMEM);
    cudaFuncSetAttribute(gemm_mma_kernel<false, float>,
                         cudaFuncAttributeMaxDynamicSharedMemorySize, SMEM);

    // 1. prep: convert activations/weights to fp16 (weights K-major)
    conv_x_kernel<<<(NROWS * KDIM / 4 + 255) / 256, 256>>>(hx);
    conv_w1_kernel<<<(EQ * KDIM + 255) / 256, 256>>>(dense_w);
    conv_w2_kernel<<<(N2P * KDIM + 255) / 256, 256>>>(theta_w, theta_b,
                                                      Theta_w, Theta_b);

    // 2. h = gelu(hx @ dense_w + dense_b) -> fp16   [M=32768, N=1280, K=1280]
    {
        dim3 grid(EQ / 128, NROWS / 128);
        gemm_mma_kernel<true, __half><<<grid, 256, SMEM>>>(xf, w1f, dense_b,
                                                           hfp, EQ);
    }

    // 3. LayerNorm (fp16 in/out, fp32 stats)
    ln_kernel<<<NROWS, 256>>>(hfp, ln_g, ln_b);

    // 4. logits2 = LN(h) @ [theta|Theta] + bias  [M=32768, N=640, K=1280]
    {
        dim3 grid(N2P / 128, NROWS / 128);
        gemm_mma_kernel<false, float><<<grid, 256, SMEM>>>(af, w2f, b2ptr,
                                                           l2ptr, N2P);
    }

    // 5. per-row epilogue -> Q, pi
    finalize_kernel<<<NROWS / 8, dim3(32, 8)>>>(vmask, qOut, piOut);
}